// round 15
// baseline (speedup 1.0000x reference)
#include <cuda_runtime.h>
#include <math.h>

#define NCH    64
#define PITCH  68
#define NBATCH 4096
#define SPD    2080
#define EPSV   1e-6f
#define BN_SC  0.9999950000375f
#define ROT_TOL 1e-6f
#define HMAT   (64 * PITCH)          // floats per matrix buffer

__device__ float g_rm[NCH * NCH];
__device__ float g_rp[NCH * NCH];
__device__ float g_vec [(size_t)NBATCH * SPD];
__device__ float g_mu  [(size_t)NBATCH * 32];
__device__ float g_lv  [(size_t)NBATCH * 32];
__device__ float g_vdec[(size_t)NBATCH * SPD];

__device__ __forceinline__ void iu_decode(int u, int& i, int& j)
{
    int lo = 0, hi = 63;
    while (lo < hi) {
        int mid = (lo + hi + 1) >> 1;
        if (((mid * (129 - mid)) >> 1) <= u) lo = mid; else hi = mid - 1;
    }
    i = lo;
    j = lo + (u - ((lo * (129 - lo)) >> 1));
}

// ---------- half-block (128-thread) 64x64 GEMM: 8x4 tile per thread ----------
// Compute into regs, block-barrier, write (dst may alias operands). Both halves
// must call in lockstep (barriers are block-wide).
template<int AP, int BP, bool BT, bool SC>
__device__ __forceinline__ void bgemm_h(const float* __restrict__ Ao,
                                        const float* __restrict__ Bo,
                                        const float* __restrict__ ksc,
                                        float* __restrict__ C, int t)
{
    const int i0 = (t >> 4) * 8, j0 = (t & 15) * 4;
    float acc[8][4];
#pragma unroll
    for (int r = 0; r < 8; r++)
#pragma unroll
        for (int c = 0; c < 4; c++) acc[r][c] = 0.f;
    for (int k = 0; k < 64; k++) {
        float b[4];
#pragma unroll
        for (int c = 0; c < 4; c++)
            b[c] = BT ? Bo[(j0 + c) * BP + k] : Bo[k * BP + j0 + c];
        float f = SC ? ksc[k] : 1.f;
#pragma unroll
        for (int r = 0; r < 8; r++) {
            float a = Ao[(i0 + r) * AP + k];
            if (SC) a *= f;
#pragma unroll
            for (int c = 0; c < 4; c++) acc[r][c] += a * b[c];
        }
    }
    __syncthreads();
#pragma unroll
    for (int r = 0; r < 8; r++)
#pragma unroll
        for (int c = 0; c < 4; c++)
            C[(i0 + r) * PITCH + j0 + c] = acc[r][c];
    __syncthreads();
}

// C = V diag(d) V^T given Vt rows = eigenvectors
__device__ __forceinline__ void bgemm_vtv_h(const float* __restrict__ Vt,
                                            const float* __restrict__ d,
                                            float* __restrict__ C, int t)
{
    const int i0 = (t >> 4) * 8, j0 = (t & 15) * 4;
    float acc[8][4];
#pragma unroll
    for (int r = 0; r < 8; r++)
#pragma unroll
        for (int c = 0; c < 4; c++) acc[r][c] = 0.f;
    for (int k = 0; k < 64; k++) {
        const float* row = Vt + k * PITCH;
        float dk = d[k];
        float b[4];
#pragma unroll
        for (int c = 0; c < 4; c++) b[c] = row[j0 + c];
#pragma unroll
        for (int r = 0; r < 8; r++) {
            float a = row[i0 + r] * dk;
#pragma unroll
            for (int c = 0; c < 4; c++) acc[r][c] += a * b[c];
        }
    }
    __syncthreads();
#pragma unroll
    for (int r = 0; r < 8; r++)
#pragma unroll
        for (int c = 0; c < 4; c++)
            C[(i0 + r) * PITCH + j0 + c] = acc[r][c];
    __syncthreads();
}

// ---------- one Jacobi sweep: half-block (4 warps) per matrix, thresholded ----------
// wh = warp-in-half (0..3). 'active' lets a converged half idle through barriers.
template<bool WITHV>
__device__ __forceinline__ void jacobi_sweep_h(float* __restrict__ A, float* __restrict__ Vt,
                                               int lane, int wh, bool active)
{
    for (int r = 0; r < 63; r++) {
        int p, q;
        if (lane == 0) { p = 63; q = r; }
        else {
            p = lane + r;      if (p >= 63) p -= 63;
            q = 63 - lane + r; if (q >= 63) q -= 63;
        }
        float c = 1.f, s = 0.f;
        if (active) {
            float app = A[p * PITCH + p], aqq = A[q * PITCH + q];
            float apq = 0.5f * (A[p * PITCH + q] + A[q * PITCH + p]);
            if (fabsf(apq) > 1e-36f) {
                float tau = (aqq - app) / (2.f * apq);
                float t = copysignf(1.f, tau) / (fabsf(tau) + sqrtf(1.f + tau * tau));
                c = rsqrtf(1.f + t * t);
                s = t * c;
                if (fabsf(s) < ROT_TOL) { c = 1.f; s = 0.f; }
            }
        }
        __syncthreads();
        if (active) {
#pragma unroll
            for (int n = 0; n < 8; n++) {
                int a = wh + 4 * n;
                float ca = __shfl_sync(0xffffffffu, c, a);
                float sa = __shfl_sync(0xffffffffu, s, a);
                int   pa = __shfl_sync(0xffffffffu, p, a);
                int   qa = __shfl_sync(0xffffffffu, q, a);
                bool rowrot = (sa != 0.f);
                if (rowrot || (s != 0.f)) {
                    float x00 = A[pa * PITCH + p], x01 = A[pa * PITCH + q];
                    float x10 = A[qa * PITCH + p], x11 = A[qa * PITCH + q];
                    float t00 = ca * x00 - sa * x10, t01 = ca * x01 - sa * x11;
                    float t10 = sa * x00 + ca * x10, t11 = sa * x01 + ca * x11;
                    A[pa * PITCH + p] = c * t00 - s * t01;
                    A[pa * PITCH + q] = s * t00 + c * t01;
                    A[qa * PITCH + p] = c * t10 - s * t11;
                    A[qa * PITCH + q] = s * t10 + c * t11;
                }
                if (WITHV && rowrot) {
                    float2* Pp = reinterpret_cast<float2*>(Vt + pa * PITCH) + lane;
                    float2* Pq = reinterpret_cast<float2*>(Vt + qa * PITCH) + lane;
                    float2 vp = *Pp, vq = *Pq;
                    float2 np, nq;
                    np.x = ca * vp.x - sa * vq.x; np.y = ca * vp.y - sa * vq.y;
                    nq.x = sa * vp.x + ca * vq.x; nq.y = sa * vp.y + ca * vq.y;
                    *Pp = np; *Pq = nq;
                }
            }
        }
        __syncthreads();
    }
}

template<bool WITHV>
__device__ void jacobi64_h(float* __restrict__ A, float* __restrict__ Vt, int sweeps,
                           int lane, int wh)
{
    for (int sw = 0; sw < sweeps; sw++)
        jacobi_sweep_h<WITHV>(A, Vt, lane, wh, true);
}

// dynamic smem: 2 halves x (A + Vt) = 4 * 64*68 floats = 69632 B -> 3 blocks/SM
#define DYN_B (4 * HMAT * (int)sizeof(float))

__global__ __launch_bounds__(256, 3)
void prep_ref_kernel(const float* __restrict__ ref,
                     float* __restrict__ rm_out, float* __restrict__ rp_out)
{
    extern __shared__ float smem[];
    int tid = threadIdx.x, lane = tid & 31;
    int h = tid >> 7, t = tid & 127, wh = (tid >> 5) & 3;
    float* A  = smem + h * 2 * HMAT;
    float* Vt = A + HMAT;
    __shared__ float w1[2][64], w2[2][64];
    // both halves redundantly solve ref (prep cost is negligible; keeps barriers symmetric)
    for (int idx = t; idx < 4096; idx += 128) {
        int i = idx >> 6, j = idx & 63;
        A[i * PITCH + j] = ref[idx] + ((i == j) ? EPSV : 0.f);
        Vt[i * PITCH + j] = (i == j) ? 1.f : 0.f;
    }
    __syncthreads();
    jacobi64_h<true>(A, Vt, 12, lane, wh);
    if (t < 64) {
        float w = fmaxf(A[t * PITCH + t], 1e-20f);
        w1[h][t] = rsqrtf(w);
        w2[h][t] = sqrtf(w);
    }
    __syncthreads();
    bgemm_vtv_h(Vt, w1[h], A, t);
    if (h == 0)
        for (int idx = t; idx < 4096; idx += 128)
            rm_out[idx] = A[(idx >> 6) * PITCH + (idx & 63)];
    __syncthreads();
    bgemm_vtv_h(Vt, w2[h], A, t);
    if (h == 0)
        for (int idx = t; idx < 4096; idx += 128)
            rp_out[idx] = A[(idx >> 6) * PITCH + (idx & 63)];
}

__global__ __launch_bounds__(256, 3)
void log_map_kernel(const float* __restrict__ x,
                    const float* __restrict__ rm, const float* __restrict__ rp,
                    float* __restrict__ vec_out)
{
    extern __shared__ float smem[];
    int tid = threadIdx.x, lane = tid & 31;
    int h = tid >> 7, t = tid & 127, wh = (tid >> 5) & 3;
    float* A  = smem + h * 2 * HMAT;
    float* Vt = A + HMAT;
    __shared__ float w[2][64];
    const size_t item = (size_t)blockIdx.x * 2 + h;
    const float* X = x + item * 4096;
    for (int idx = t; idx < 1024; idx += 128) {
        int i = idx >> 4, j4 = (idx & 15) << 2;
        *(float4*)(A + i * PITCH + j4) = *(const float4*)(X + i * 64 + j4);
    }
    __syncthreads();
    bgemm_h<64, PITCH, false, false>(rm, A, nullptr, Vt, t);   // Vt = rm @ x
    bgemm_h<PITCH, 64, false, false>(Vt, rm, nullptr, A, t);   // A = s = rm x rm
    for (int idx = t; idx < 4096; idx += 128) {
        int i = idx >> 6, j = idx & 63;
        Vt[i * PITCH + j] = (i == j) ? 1.f : 0.f;
    }
    __syncthreads();
    jacobi64_h<true>(A, Vt, 7, lane, wh);
    if (t < 64) w[h][t] = logf(fmaxf(A[t * PITCH + t], 1e-12f));
    __syncthreads();
    bgemm_vtv_h(Vt, w[h], A, t);                               // A = log_s
    bgemm_h<64, PITCH, false, false>(rm, A, nullptr, A, t);    // A = rm @ log_s
    bgemm_h<PITCH, 64, false, false>(A, rp, nullptr, A, t);    // A = tang
    float* out = vec_out + item * SPD;
    for (int u = t; u < SPD; u += 128) {
        int i, j; iu_decode(u, i, j);
        out[u] = A[i * PITCH + j];
    }
}

__global__ __launch_bounds__(256, 3)
void exp_map_kernel(const float* __restrict__ ref,
                    const float* __restrict__ vdec_in,
                    float* __restrict__ recon)
{
    extern __shared__ float smem[];
    int tid = threadIdx.x, lane = tid & 31;
    int h = tid >> 7, t = tid & 127, wh = (tid >> 5) & 3;
    float* A  = smem + h * 2 * HMAT;
    float* Vt = A + HMAT;
    __shared__ float w[2][64];
    __shared__ float red[2][64];
    __shared__ float sh_shift[2];
    __shared__ int s_done[2], s_break;
    const size_t item = (size_t)blockIdx.x * 2 + h;
    const float* vd = vdec_in + item * SPD;
    for (int u = t; u < SPD; u += 128) {
        int i, j; iu_decode(u, i, j);
        float v = vd[u];
        if (i == j) A[i * PITCH + i] = v + EPSV;
        else { A[i * PITCH + j] = v; A[j * PITCH + i] = v; }
    }
    for (int idx = t; idx < 4096; idx += 128) {
        int i = idx >> 6, j = idx & 63;
        Vt[i * PITCH + j] = (i == j) ? 1.f : 0.f;
    }
    __syncthreads();
    jacobi64_h<true>(A, Vt, 8, lane, wh);
    if (t < 64) w[h][t] = expf(A[t * PITCH + t]);
    __syncthreads();
    bgemm_h<64, PITCH, true, false>(ref, Vt, nullptr, A, t);    // A = U = ref @ V
    bgemm_h<PITCH, PITCH, false, true>(A, Vt, w[h], A, t);      // A = R = U e^w V^T
    for (int idx = t; idx < 4096; idx += 128) {
        int i = idx >> 6, j = idx & 63;
        Vt[i * PITCH + j] = (i >= j) ? A[i * PITCH + j] : A[j * PITCH + i];
    }
    if (tid == 0) s_break = 0;
    if (t == 0) s_done[h] = 0;
    __syncthreads();
    // values-only eigensolve on sym_lower(R) with Gershgorin shift=0 certification.
    // Both halves iterate in lock-step; a certified half idles through barriers.
    float shf = 0.f;
    {
        for (int sw = 0; sw < 8 && !s_break; sw++) {
            bool active = !s_done[h];
            jacobi_sweep_h<false>(Vt, nullptr, lane, wh, active);
            if (sw >= 2) {
                // per-half Gershgorin: 2 threads per row, 32 cols each
                int row = t >> 1, c0 = (t & 1) * 32;
                float part = 0.f;
                if (active) {
                    for (int j = 0; j < 32; j++) {
                        int col = c0 + j;
                        float v = Vt[row * PITCH + col];
                        part += (col == row) ? 0.f : fabsf(v);
                    }
                    part += __shfl_xor_sync(0xffffffffu, part, 1);
                    if ((t & 1) == 0) red[h][row] = Vt[row * PITCH + row] - part;
                }
                __syncthreads();
                if (t == 0 && active) {
                    float m = red[h][0];
                    for (int i = 1; i < 64; i++) m = fminf(m, red[h][i]);
                    s_done[h] = (m > EPSV) ? 1 : 0;
                }
                __syncthreads();
                if (tid == 0) s_break = (s_done[0] && s_done[1]) ? 1 : 0;
                __syncthreads();
            }
        }
        if (!s_done[h]) {
            if (t == 0) {
                float m = Vt[0];
                for (int k = 1; k < 64; k++) m = fminf(m, Vt[k * PITCH + k]);
                sh_shift[h] = fmaxf(EPSV - m, 0.f);
            }
            __syncthreads();
            shf = sh_shift[h];
        }
    }
    float* out = recon + item * 4096;
    for (int idx = t; idx < 1024; idx += 128) {
        int i = idx >> 4, j4 = (idx & 15) << 2;
        float4 v = *(const float4*)(A + i * PITCH + j4);
        if (i >= j4 && i < j4 + 4) ((float*)&v)[i - j4] += shf;
        *(float4*)(out + i * 64 + j4) = v;
    }
}

// ---------------- fused MLP: 4 items per 128-thread block (W reuse) ----------------
__global__ void mlp_fused_kernel(
    const float* __restrict__ vec,
    const float* __restrict__ W1, const float* __restrict__ b1,
    const float* __restrict__ g1, const float* __restrict__ bb1,
    const float* __restrict__ W2, const float* __restrict__ b2,
    const float* __restrict__ g2, const float* __restrict__ bb2,
    const float* __restrict__ Wmu, const float* __restrict__ bmu,
    const float* __restrict__ Wlv, const float* __restrict__ blv,
    const float* __restrict__ D1, const float* __restrict__ db1,
    const float* __restrict__ dg1, const float* __restrict__ dbb1,
    const float* __restrict__ D2, const float* __restrict__ db2,
    const float* __restrict__ dg2, const float* __restrict__ dbb2,
    const float* __restrict__ D3, const float* __restrict__ db3,
    float* __restrict__ mu_out, float* __restrict__ lv_out,
    float* __restrict__ vdec_out)
{
    __shared__ float sv[4][SPD];
    __shared__ float h1[4][128], h2[4][64], zz[4][32], d1[4][64], d2[4][128];
    const int tid = threadIdx.x;
    const size_t b0 = (size_t)blockIdx.x * 4;
#pragma unroll
    for (int it = 0; it < 4; it++)
        for (int u = tid; u < SPD; u += 128) sv[it][u] = vec[(b0 + it) * SPD + u];
    __syncthreads();
    {
        float a0 = 0.f, a1 = 0.f, a2 = 0.f, a3 = 0.f;
        const float* wr = W1 + (size_t)tid * SPD;
        for (int k = 0; k < SPD; k++) {
            float wv = wr[k];
            a0 += sv[0][k] * wv; a1 += sv[1][k] * wv;
            a2 += sv[2][k] * wv; a3 += sv[3][k] * wv;
        }
        float bs = b1[tid], scl = g1[tid] * BN_SC, sh = bb1[tid];
        float u;
        u = a0 + bs; u = (u >= 0.f) ? u : 0.2f * u; h1[0][tid] = u * scl + sh;
        u = a1 + bs; u = (u >= 0.f) ? u : 0.2f * u; h1[1][tid] = u * scl + sh;
        u = a2 + bs; u = (u >= 0.f) ? u : 0.2f * u; h1[2][tid] = u * scl + sh;
        u = a3 + bs; u = (u >= 0.f) ? u : 0.2f * u; h1[3][tid] = u * scl + sh;
    }
    __syncthreads();
    if (tid < 64) {
        float a0 = 0.f, a1 = 0.f, a2 = 0.f, a3 = 0.f;
        const float* wr = W2 + tid * 128;
        for (int k = 0; k < 128; k++) {
            float wv = wr[k];
            a0 += h1[0][k] * wv; a1 += h1[1][k] * wv;
            a2 += h1[2][k] * wv; a3 += h1[3][k] * wv;
        }
        float bs = b2[tid], scl = g2[tid] * BN_SC, sh = bb2[tid];
        float u;
        u = a0 + bs; u = (u >= 0.f) ? u : 0.2f * u; h2[0][tid] = u * scl + sh;
        u = a1 + bs; u = (u >= 0.f) ? u : 0.2f * u; h2[1][tid] = u * scl + sh;
        u = a2 + bs; u = (u >= 0.f) ? u : 0.2f * u; h2[2][tid] = u * scl + sh;
        u = a3 + bs; u = (u >= 0.f) ? u : 0.2f * u; h2[3][tid] = u * scl + sh;
    }
    __syncthreads();
    if (tid < 32) {
        float am[4] = {0.f, 0.f, 0.f, 0.f}, al[4] = {0.f, 0.f, 0.f, 0.f};
        const float* wm = Wmu + tid * 64;
        const float* wl = Wlv + tid * 64;
        for (int k = 0; k < 64; k++) {
            float wmv = wm[k], wlv_ = wl[k];
#pragma unroll
            for (int it = 0; it < 4; it++) {
                am[it] += h2[it][k] * wmv;
                al[it] += h2[it][k] * wlv_;
            }
        }
        float bm = bmu[tid], bl = blv[tid];
#pragma unroll
        for (int it = 0; it < 4; it++) {
            float m = am[it] + bm;
            zz[it][tid] = m;
            mu_out[(b0 + it) * 32 + tid] = m;
            lv_out[(b0 + it) * 32 + tid] = al[it] + bl;
        }
    }
    __syncthreads();
    if (tid < 64) {
        float a[4] = {0.f, 0.f, 0.f, 0.f};
        const float* wr = D1 + tid * 32;
        for (int k = 0; k < 32; k++) {
            float wv = wr[k];
#pragma unroll
            for (int it = 0; it < 4; it++) a[it] += zz[it][k] * wv;
        }
        float bs = db1[tid], scl = dg1[tid] * BN_SC, sh = dbb1[tid];
#pragma unroll
        for (int it = 0; it < 4; it++) {
            float u = a[it] + bs; u = (u >= 0.f) ? u : 0.2f * u;
            d1[it][tid] = u * scl + sh;
        }
    }
    __syncthreads();
    {
        float a[4] = {0.f, 0.f, 0.f, 0.f};
        const float* wr = D2 + tid * 64;
        for (int k = 0; k < 64; k++) {
            float wv = wr[k];
#pragma unroll
            for (int it = 0; it < 4; it++) a[it] += d1[it][k] * wv;
        }
        float bs = db2[tid], scl = dg2[tid] * BN_SC, sh = dbb2[tid];
#pragma unroll
        for (int it = 0; it < 4; it++) {
            float u = a[it] + bs; u = (u >= 0.f) ? u : 0.2f * u;
            d2[it][tid] = u * scl + sh;
        }
    }
    __syncthreads();
    for (int j = tid; j < SPD; j += 128) {
        float a0 = 0.f, a1 = 0.f, a2 = 0.f, a3 = 0.f;
        const float* wr = D3 + (size_t)j * 128;
        for (int k = 0; k < 128; k++) {
            float wv = wr[k];
            a0 += d2[0][k] * wv; a1 += d2[1][k] * wv;
            a2 += d2[2][k] * wv; a3 += d2[3][k] * wv;
        }
        float bs = db3[j];
        vdec_out[(b0 + 0) * SPD + j] = a0 + bs;
        vdec_out[(b0 + 1) * SPD + j] = a1 + bs;
        vdec_out[(b0 + 2) * SPD + j] = a2 + bs;
        vdec_out[(b0 + 3) * SPD + j] = a3 + bs;
    }
}

extern "C" void kernel_launch(void* const* d_in, const int* in_sizes, int n_in,
                              void* d_out, int out_size)
{
    const float* x      = (const float*)d_in[0];
    const float* ref    = (const float*)d_in[1];
    const float* enc_w1 = (const float*)d_in[2];
    const float* enc_b1 = (const float*)d_in[3];
    const float* bn1_g  = (const float*)d_in[4];
    const float* bn1_b  = (const float*)d_in[5];
    const float* enc_w2 = (const float*)d_in[6];
    const float* enc_b2 = (const float*)d_in[7];
    const float* bn2_g  = (const float*)d_in[8];
    const float* bn2_b  = (const float*)d_in[9];
    const float* mu_w   = (const float*)d_in[10];
    const float* mu_b   = (const float*)d_in[11];
    const float* lv_w   = (const float*)d_in[12];
    const float* lv_b   = (const float*)d_in[13];
    const float* dec_w1 = (const float*)d_in[14];
    const float* dec_b1 = (const float*)d_in[15];
    const float* dbn1_g = (const float*)d_in[16];
    const float* dbn1_b = (const float*)d_in[17];
    const float* dec_w2 = (const float*)d_in[18];
    const float* dec_b2 = (const float*)d_in[19];
    const float* dbn2_g = (const float*)d_in[20];
    const float* dbn2_b = (const float*)d_in[21];
    const float* dec_w3 = (const float*)d_in[22];
    const float* dec_b3 = (const float*)d_in[23];

    float* out = (float*)d_out;

    float *p_rm, *p_rp, *p_vec, *p_mu, *p_lv, *p_vdec;
    cudaGetSymbolAddress((void**)&p_rm,   g_rm);
    cudaGetSymbolAddress((void**)&p_rp,   g_rp);
    cudaGetSymbolAddress((void**)&p_vec,  g_vec);
    cudaGetSymbolAddress((void**)&p_mu,   g_mu);
    cudaGetSymbolAddress((void**)&p_lv,   g_lv);
    cudaGetSymbolAddress((void**)&p_vdec, g_vdec);

    cudaFuncSetAttribute(prep_ref_kernel, cudaFuncAttributeMaxDynamicSharedMemorySize, DYN_B);
    cudaFuncSetAttribute(log_map_kernel,  cudaFuncAttributeMaxDynamicSharedMemorySize, DYN_B);
    cudaFuncSetAttribute(exp_map_kernel,  cudaFuncAttributeMaxDynamicSharedMemorySize, DYN_B);

    const long long need = (long long)NBATCH * 4096 + 2LL * NBATCH * 32;  // 17039360
    float* mu_dst = ((long long)out_size == need) ? out + (size_t)NBATCH * 4096 : p_mu;
    float* lv_dst = ((long long)out_size == need) ? out + (size_t)NBATCH * 4096 + (size_t)NBATCH * 32 : p_lv;

    prep_ref_kernel<<<1, 256, DYN_B>>>(ref, p_rm, p_rp);
    log_map_kernel<<<NBATCH / 2, 256, DYN_B>>>(x, p_rm, p_rp, p_vec);

    mlp_fused_kernel<<<NBATCH / 4, 128>>>(p_vec,
        enc_w1, enc_b1, bn1_g, bn1_b,
        enc_w2, enc_b2, bn2_g, bn2_b,
        mu_w, mu_b, lv_w, lv_b,
        dec_w1, dec_b1, dbn1_g, dbn1_b,
        dec_w2, dec_b2, dbn2_g, dbn2_b,
        dec_w3, dec_b3,
        mu_dst, lv_dst, p_vdec);

    exp_map_kernel<<<NBATCH / 2, 256, DYN_B>>>(ref, p_vdec, out);
}

// round 16
// speedup vs baseline: 1.6891x; 1.6891x over previous
#include <cuda_runtime.h>
#include <math.h>

#define NCH    64
#define PITCH  68
#define NBATCH 4096
#define SPD    2080
#define EPSV   1e-6f
#define BN_SC  0.9999950000375f
#define ROT_TOL 1e-6f
#define HMAT   (64 * PITCH)

__device__ float g_rm[NCH * NCH];
__device__ float g_rp[NCH * NCH];
__device__ float g_vec [(size_t)NBATCH * SPD];
__device__ float g_mu  [(size_t)NBATCH * 32];
__device__ float g_lv  [(size_t)NBATCH * 32];
__device__ float g_vdec[(size_t)NBATCH * SPD];

__device__ __forceinline__ void iu_decode(int u, int& i, int& j)
{
    int lo = 0, hi = 63;
    while (lo < hi) {
        int mid = (lo + hi + 1) >> 1;
        if (((mid * (129 - mid)) >> 1) <= u) lo = mid; else hi = mid - 1;
    }
    i = lo;
    j = lo + (u - ((lo * (129 - lo)) >> 1));
}

// ---------- 256-thread 64x64 GEMM, scalar loads, in-place capable (barrier protocol) ----------
template<int AP, int BP, bool BT, bool SC>
__device__ __forceinline__ void bgemm(const float* __restrict__ Ao,
                                      const float* __restrict__ Bo,
                                      const float* __restrict__ ksc,
                                      float* __restrict__ C, int tid)
{
    const int i0 = (tid >> 4) * 4, j0 = (tid & 15) * 4;
    float acc[4][4];
#pragma unroll
    for (int r = 0; r < 4; r++)
#pragma unroll
        for (int c = 0; c < 4; c++) acc[r][c] = 0.f;
    for (int k = 0; k < 64; k++) {
        float a[4], b[4];
#pragma unroll
        for (int r = 0; r < 4; r++) a[r] = Ao[(i0 + r) * AP + k];
        if (SC) {
            float f = ksc[k];
#pragma unroll
            for (int r = 0; r < 4; r++) a[r] *= f;
        }
#pragma unroll
        for (int c = 0; c < 4; c++)
            b[c] = BT ? Bo[(j0 + c) * BP + k] : Bo[k * BP + j0 + c];
#pragma unroll
        for (int r = 0; r < 4; r++)
#pragma unroll
            for (int c = 0; c < 4; c++) acc[r][c] += a[r] * b[c];
    }
    __syncthreads();
#pragma unroll
    for (int r = 0; r < 4; r++)
#pragma unroll
        for (int c = 0; c < 4; c++)
            C[(i0 + r) * PITCH + j0 + c] = acc[r][c];
    __syncthreads();
}

__device__ __forceinline__ void bgemm_vtv(const float* __restrict__ Vt,
                                          const float* __restrict__ d,
                                          float* __restrict__ C, int tid)
{
    const int i0 = (tid >> 4) * 4, j0 = (tid & 15) * 4;
    float acc[4][4];
#pragma unroll
    for (int r = 0; r < 4; r++)
#pragma unroll
        for (int c = 0; c < 4; c++) acc[r][c] = 0.f;
    for (int t = 0; t < 64; t++) {
        const float* row = Vt + t * PITCH;
        float dk = d[t];
        float a[4], b[4];
#pragma unroll
        for (int r = 0; r < 4; r++) a[r] = row[i0 + r] * dk;
#pragma unroll
        for (int c = 0; c < 4; c++) b[c] = row[j0 + c];
#pragma unroll
        for (int r = 0; r < 4; r++)
#pragma unroll
            for (int c = 0; c < 4; c++) acc[r][c] += a[r] * b[c];
    }
    __syncthreads();
#pragma unroll
    for (int r = 0; r < 4; r++)
#pragma unroll
        for (int c = 0; c < 4; c++)
            C[(i0 + r) * PITCH + j0 + c] = acc[r][c];
    __syncthreads();
}

// ---------- float4 in-place GEMM: C = alpha*(A@B) + (ADDI ? I : 0) ----------
template<int AP, int BP, bool ADDI>
__device__ __forceinline__ void bgemm_f4(const float* __restrict__ Ao,
                                         const float* __restrict__ Bo,
                                         float alpha, float* __restrict__ C, int tid)
{
    const int i0 = (tid >> 4) * 4, j0 = (tid & 15) * 4;
    float acc[4][4];
#pragma unroll
    for (int r = 0; r < 4; r++)
#pragma unroll
        for (int c = 0; c < 4; c++) acc[r][c] = 0.f;
    for (int k4 = 0; k4 < 64; k4 += 4) {
        float4 a[4], br[4];
#pragma unroll
        for (int r = 0; r < 4; r++) a[r] = *(const float4*)(Ao + (i0 + r) * AP + k4);
#pragma unroll
        for (int kk = 0; kk < 4; kk++) br[kk] = *(const float4*)(Bo + (k4 + kk) * BP + j0);
#pragma unroll
        for (int r = 0; r < 4; r++) {
            acc[r][0] += a[r].x * br[0].x + a[r].y * br[1].x + a[r].z * br[2].x + a[r].w * br[3].x;
            acc[r][1] += a[r].x * br[0].y + a[r].y * br[1].y + a[r].z * br[2].y + a[r].w * br[3].y;
            acc[r][2] += a[r].x * br[0].z + a[r].y * br[1].z + a[r].z * br[2].z + a[r].w * br[3].z;
            acc[r][3] += a[r].x * br[0].w + a[r].y * br[1].w + a[r].z * br[2].w + a[r].w * br[3].w;
        }
    }
    __syncthreads();
#pragma unroll
    for (int r = 0; r < 4; r++)
#pragma unroll
        for (int c = 0; c < 4; c++) {
            float v = acc[r][c] * alpha;
            if (ADDI && (i0 + r == j0 + c)) v += 1.f;
            C[(i0 + r) * PITCH + j0 + c] = v;
        }
    __syncthreads();
}

// ---------- one parallel-order Jacobi sweep (256 threads, thresholded) ----------
template<bool WITHV>
__device__ __forceinline__ void jacobi_sweep(float* __restrict__ A, float* __restrict__ Vt,
                                             int lane, int warp)
{
    for (int r = 0; r < 63; r++) {
        int p, q;
        if (lane == 0) { p = 63; q = r; }
        else {
            p = lane + r;      if (p >= 63) p -= 63;
            q = 63 - lane + r; if (q >= 63) q -= 63;
        }
        float app = A[p * PITCH + p], aqq = A[q * PITCH + q];
        float apq = 0.5f * (A[p * PITCH + q] + A[q * PITCH + p]);
        float c = 1.f, s = 0.f;
        if (fabsf(apq) > 1e-36f) {
            float tau = (aqq - app) / (2.f * apq);
            float t = copysignf(1.f, tau) / (fabsf(tau) + sqrtf(1.f + tau * tau));
            c = rsqrtf(1.f + t * t);
            s = t * c;
            if (fabsf(s) < ROT_TOL) { c = 1.f; s = 0.f; }
        }
        __syncthreads();
#pragma unroll
        for (int n = 0; n < 4; n++) {
            int a = warp + 8 * n;
            float ca = __shfl_sync(0xffffffffu, c, a);
            float sa = __shfl_sync(0xffffffffu, s, a);
            int   pa = __shfl_sync(0xffffffffu, p, a);
            int   qa = __shfl_sync(0xffffffffu, q, a);
            bool rowrot = (sa != 0.f);
            if (rowrot || (s != 0.f)) {
                float x00 = A[pa * PITCH + p], x01 = A[pa * PITCH + q];
                float x10 = A[qa * PITCH + p], x11 = A[qa * PITCH + q];
                float t00 = ca * x00 - sa * x10, t01 = ca * x01 - sa * x11;
                float t10 = sa * x00 + ca * x10, t11 = sa * x01 + ca * x11;
                A[pa * PITCH + p] = c * t00 - s * t01;
                A[pa * PITCH + q] = s * t00 + c * t01;
                A[qa * PITCH + p] = c * t10 - s * t11;
                A[qa * PITCH + q] = s * t10 + c * t11;
            }
            if (WITHV && rowrot) {
                float2* Pp = reinterpret_cast<float2*>(Vt + pa * PITCH) + lane;
                float2* Pq = reinterpret_cast<float2*>(Vt + qa * PITCH) + lane;
                float2 vp = *Pp, vq = *Pq;
                float2 np, nq;
                np.x = ca * vp.x - sa * vq.x; np.y = ca * vp.y - sa * vq.y;
                nq.x = sa * vp.x + ca * vq.x; nq.y = sa * vp.y + ca * vq.y;
                *Pp = np; *Pq = nq;
            }
        }
        __syncthreads();
    }
}

template<bool WITHV>
__device__ void jacobi64(float* __restrict__ A, float* __restrict__ Vt, int sweeps,
                         int lane, int warp)
{
    for (int sw = 0; sw < sweeps; sw++)
        jacobi_sweep<WITHV>(A, Vt, lane, warp);
}

#define DYN_B (2 * HMAT * (int)sizeof(float))   // 34816 B

__global__ __launch_bounds__(256, 6)
void prep_ref_kernel(const float* __restrict__ ref,
                     float* __restrict__ rm_out, float* __restrict__ rp_out)
{
    extern __shared__ float smem[];
    float* A  = smem;
    float* Vt = smem + HMAT;
    __shared__ float w1[64], w2[64];
    int tid = threadIdx.x, lane = tid & 31, warp = tid >> 5;
    for (int idx = tid; idx < 4096; idx += 256) {
        int i = idx >> 6, j = idx & 63;
        A[i * PITCH + j] = ref[idx] + ((i == j) ? EPSV : 0.f);
        Vt[i * PITCH + j] = (i == j) ? 1.f : 0.f;
    }
    __syncthreads();
    jacobi64<true>(A, Vt, 12, lane, warp);
    if (tid < 64) {
        float w = fmaxf(A[tid * PITCH + tid], 1e-20f);
        w1[tid] = rsqrtf(w);
        w2[tid] = sqrtf(w);
    }
    __syncthreads();
    bgemm_vtv(Vt, w1, A, tid);
    for (int idx = tid; idx < 4096; idx += 256)
        rm_out[idx] = A[(idx >> 6) * PITCH + (idx & 63)];
    __syncthreads();
    bgemm_vtv(Vt, w2, A, tid);
    for (int idx = tid; idx < 4096; idx += 256)
        rp_out[idx] = A[(idx >> 6) * PITCH + (idx & 63)];
}

__global__ __launch_bounds__(256, 6)
void log_map_kernel(const float* __restrict__ x,
                    const float* __restrict__ rm, const float* __restrict__ rp,
                    float* __restrict__ vec_out)
{
    extern __shared__ float smem[];
    float* A  = smem;
    float* Vt = smem + HMAT;
    __shared__ float w[64];
    int tid = threadIdx.x, lane = tid & 31, warp = tid >> 5;
    const float* X = x + (size_t)blockIdx.x * 4096;
    for (int idx = tid; idx < 1024; idx += 256) {
        int i = idx >> 4, j4 = (idx & 15) << 2;
        *(float4*)(A + i * PITCH + j4) = *(const float4*)(X + i * 64 + j4);
    }
    __syncthreads();
    bgemm<64, PITCH, false, false>(rm, A, nullptr, Vt, tid);   // Vt = rm @ x
    bgemm<PITCH, 64, false, false>(Vt, rm, nullptr, A, tid);   // A = s = rm x rm
    for (int idx = tid; idx < 4096; idx += 256) {
        int i = idx >> 6, j = idx & 63;
        Vt[i * PITCH + j] = (i == j) ? 1.f : 0.f;
    }
    __syncthreads();
    jacobi64<true>(A, Vt, 7, lane, warp);
    if (tid < 64) w[tid] = logf(fmaxf(A[tid * PITCH + tid], 1e-12f));
    __syncthreads();
    bgemm_vtv(Vt, w, A, tid);                                  // A = log_s
    bgemm<64, PITCH, false, false>(rm, A, nullptr, A, tid);    // A = rm @ log_s
    bgemm<PITCH, 64, false, false>(A, rp, nullptr, A, tid);    // A = tang
    float* out = vec_out + (size_t)blockIdx.x * SPD;
    for (int u = tid; u < SPD; u += 256) {
        int i, j; iu_decode(u, i, j);
        out[u] = A[i * PITCH + j];
    }
}

// ---------------- exp_map via scaling-and-squaring + Cholesky PD certificate ----------------
__global__ __launch_bounds__(256, 4)
void exp_map_kernel(const float* __restrict__ ref,
                    const float* __restrict__ vdec_in,
                    float* __restrict__ recon)
{
    extern __shared__ float smem[];
    float* B = smem;          // scaled m; later R
    float* X = smem + HMAT;   // Taylor/squaring accumulator; later test buffer
    __shared__ float colk[64];
    __shared__ float sh_shift;
    __shared__ int s_fail;
    int tid = threadIdx.x, lane = tid & 31, warp = tid >> 5;
    const float* vd = vdec_in + (size_t)blockIdx.x * SPD;
    const float SCL = 1.f / 64.f;   // 2^-6 scaling

    // B = (m + eps I) / 64 (symmetric), X = I
    for (int u = tid; u < SPD; u += 256) {
        int i, j; iu_decode(u, i, j);
        float v = vd[u];
        if (i == j) B[i * PITCH + i] = (v + EPSV) * SCL;
        else { float sv = v * SCL; B[i * PITCH + j] = sv; B[j * PITCH + i] = sv; }
    }
    for (int idx = tid; idx < 4096; idx += 256) {
        int i = idx >> 6, j = idx & 63;
        X[i * PITCH + j] = (i == j) ? 1.f : 0.f;
    }
    if (tid == 0) s_fail = 0;
    __syncthreads();

    // Horner Taylor order 6: X <- (B*X)/k + I, k = 6..1  ->  X = sum_{j<=6} B^j/j!
#pragma unroll
    for (int k = 6; k >= 1; k--)
        bgemm_f4<PITCH, PITCH, true>(B, X, 1.f / (float)k, X, tid);
    // 6 squarings: X <- X*X  ->  X = exp(m + eps I)
#pragma unroll
    for (int q = 0; q < 6; q++)
        bgemm_f4<PITCH, PITCH, false>(X, X, 1.f, X, tid);

    // B = R = ref @ exp_a
    bgemm_f4<64, PITCH, false>(ref, X, 1.f, B, tid);

    // X = sym_lower(R) - eps I  (PD test matrix)
    for (int idx = tid; idx < 4096; idx += 256) {
        int i = idx >> 6, j = idx & 63;
        float v = (i >= j) ? B[i * PITCH + j] : B[j * PITCH + i];
        X[i * PITCH + j] = v - ((i == j) ? EPSV : 0.f);
    }
    __syncthreads();

    // Cholesky-style PD certificate (full-square trailing update keeps symmetry)
    for (int k = 0; k < 64; k++) {
        float piv = X[k * PITCH + k];          // uniform read
        if (piv < 1e-5f) {
            if (tid == 0) s_fail = 1;
            __syncthreads();
            break;
        }
        if (tid > k && tid < 64) colk[tid] = X[tid * PITCH + k];
        __syncthreads();
        int n = 63 - k;
        if (n > 0) {
            float inv = 1.f / piv;
            for (int idx = tid; idx < n * n; idx += 256) {
                int i = k + 1 + idx / n, j = k + 1 + idx % n;
                X[i * PITCH + j] -= colk[i] * colk[j] * inv;
            }
        }
        __syncthreads();
    }

    float shf = 0.f;
    if (s_fail) {
        // fallback: full values-only Jacobi on sym_lower(R)
        for (int idx = tid; idx < 4096; idx += 256) {
            int i = idx >> 6, j = idx & 63;
            X[i * PITCH + j] = (i >= j) ? B[i * PITCH + j] : B[j * PITCH + i];
        }
        __syncthreads();
        for (int sw = 0; sw < 8; sw++)
            jacobi_sweep<false>(X, nullptr, lane, warp);
        if (tid == 0) {
            float m = X[0];
            for (int t = 1; t < 64; t++) m = fminf(m, X[t * PITCH + t]);
            sh_shift = fmaxf(EPSV - m, 0.f);
        }
        __syncthreads();
        shf = sh_shift;
    }

    float* out = recon + (size_t)blockIdx.x * 4096;
    for (int idx = tid; idx < 1024; idx += 256) {
        int i = idx >> 4, j4 = (idx & 15) << 2;
        float4 v = *(const float4*)(B + i * PITCH + j4);
        if (i >= j4 && i < j4 + 4) ((float*)&v)[i - j4] += shf;
        *(float4*)(out + i * 64 + j4) = v;
    }
}

// ---------------- fused MLP: 4 items per 128-thread block (W reuse) ----------------
__global__ void mlp_fused_kernel(
    const float* __restrict__ vec,
    const float* __restrict__ W1, const float* __restrict__ b1,
    const float* __restrict__ g1, const float* __restrict__ bb1,
    const float* __restrict__ W2, const float* __restrict__ b2,
    const float* __restrict__ g2, const float* __restrict__ bb2,
    const float* __restrict__ Wmu, const float* __restrict__ bmu,
    const float* __restrict__ Wlv, const float* __restrict__ blv,
    const float* __restrict__ D1, const float* __restrict__ db1,
    const float* __restrict__ dg1, const float* __restrict__ dbb1,
    const float* __restrict__ D2, const float* __restrict__ db2,
    const float* __restrict__ dg2, const float* __restrict__ dbb2,
    const float* __restrict__ D3, const float* __restrict__ db3,
    float* __restrict__ mu_out, float* __restrict__ lv_out,
    float* __restrict__ vdec_out)
{
    __shared__ float sv[4][SPD];
    __shared__ float h1[4][128], h2[4][64], zz[4][32], d1[4][64], d2[4][128];
    const int tid = threadIdx.x;
    const size_t b0 = (size_t)blockIdx.x * 4;
#pragma unroll
    for (int it = 0; it < 4; it++)
        for (int u = tid; u < SPD; u += 128) sv[it][u] = vec[(b0 + it) * SPD + u];
    __syncthreads();
    {
        float a0 = 0.f, a1 = 0.f, a2 = 0.f, a3 = 0.f;
        const float* wr = W1 + (size_t)tid * SPD;
        for (int k = 0; k < SPD; k++) {
            float wv = wr[k];
            a0 += sv[0][k] * wv; a1 += sv[1][k] * wv;
            a2 += sv[2][k] * wv; a3 += sv[3][k] * wv;
        }
        float bs = b1[tid], scl = g1[tid] * BN_SC, sh = bb1[tid];
        float u;
        u = a0 + bs; u = (u >= 0.f) ? u : 0.2f * u; h1[0][tid] = u * scl + sh;
        u = a1 + bs; u = (u >= 0.f) ? u : 0.2f * u; h1[1][tid] = u * scl + sh;
        u = a2 + bs; u = (u >= 0.f) ? u : 0.2f * u; h1[2][tid] = u * scl + sh;
        u = a3 + bs; u = (u >= 0.f) ? u : 0.2f * u; h1[3][tid] = u * scl + sh;
    }
    __syncthreads();
    if (tid < 64) {
        float a0 = 0.f, a1 = 0.f, a2 = 0.f, a3 = 0.f;
        const float* wr = W2 + tid * 128;
        for (int k = 0; k < 128; k++) {
            float wv = wr[k];
            a0 += h1[0][k] * wv; a1 += h1[1][k] * wv;
            a2 += h1[2][k] * wv; a3 += h1[3][k] * wv;
        }
        float bs = b2[tid], scl = g2[tid] * BN_SC, sh = bb2[tid];
        float u;
        u = a0 + bs; u = (u >= 0.f) ? u : 0.2f * u; h2[0][tid] = u * scl + sh;
        u = a1 + bs; u = (u >= 0.f) ? u : 0.2f * u; h2[1][tid] = u * scl + sh;
        u = a2 + bs; u = (u >= 0.f) ? u : 0.2f * u; h2[2][tid] = u * scl + sh;
        u = a3 + bs; u = (u >= 0.f) ? u : 0.2f * u; h2[3][tid] = u * scl + sh;
    }
    __syncthreads();
    if (tid < 32) {
        float am[4] = {0.f, 0.f, 0.f, 0.f}, al[4] = {0.f, 0.f, 0.f, 0.f};
        const float* wm = Wmu + tid * 64;
        const float* wl = Wlv + tid * 64;
        for (int k = 0; k < 64; k++) {
            float wmv = wm[k], wlv_ = wl[k];
#pragma unroll
            for (int it = 0; it < 4; it++) {
                am[it] += h2[it][k] * wmv;
                al[it] += h2[it][k] * wlv_;
            }
        }
        float bm = bmu[tid], bl = blv[tid];
#pragma unroll
        for (int it = 0; it < 4; it++) {
            float m = am[it] + bm;
            zz[it][tid] = m;
            mu_out[(b0 + it) * 32 + tid] = m;
            lv_out[(b0 + it) * 32 + tid] = al[it] + bl;
        }
    }
    __syncthreads();
    if (tid < 64) {
        float a[4] = {0.f, 0.f, 0.f, 0.f};
        const float* wr = D1 + tid * 32;
        for (int k = 0; k < 32; k++) {
            float wv = wr[k];
#pragma unroll
            for (int it = 0; it < 4; it++) a[it] += zz[it][k] * wv;
        }
        float bs = db1[tid], scl = dg1[tid] * BN_SC, sh = dbb1[tid];
#pragma unroll
        for (int it = 0; it < 4; it++) {
            float u = a[it] + bs; u = (u >= 0.f) ? u : 0.2f * u;
            d1[it][tid] = u * scl + sh;
        }
    }
    __syncthreads();
    {
        float a[4] = {0.f, 0.f, 0.f, 0.f};
        const float* wr = D2 + tid * 64;
        for (int k = 0; k < 64; k++) {
            float wv = wr[k];
#pragma unroll
            for (int it = 0; it < 4; it++) a[it] += d1[it][k] * wv;
        }
        float bs = db2[tid], scl = dg2[tid] * BN_SC, sh = dbb2[tid];
#pragma unroll
        for (int it = 0; it < 4; it++) {
            float u = a[it] + bs; u = (u >= 0.f) ? u : 0.2f * u;
            d2[it][tid] = u * scl + sh;
        }
    }
    __syncthreads();
    for (int j = tid; j < SPD; j += 128) {
        float a0 = 0.f, a1 = 0.f, a2 = 0.f, a3 = 0.f;
        const float* wr = D3 + (size_t)j * 128;
        for (int k = 0; k < 128; k++) {
            float wv = wr[k];
            a0 += d2[0][k] * wv; a1 += d2[1][k] * wv;
            a2 += d2[2][k] * wv; a3 += d2[3][k] * wv;
        }
        float bs = db3[j];
        vdec_out[(b0 + 0) * SPD + j] = a0 + bs;
        vdec_out[(b0 + 1) * SPD + j] = a1 + bs;
        vdec_out[(b0 + 2) * SPD + j] = a2 + bs;
        vdec_out[(b0 + 3) * SPD + j] = a3 + bs;
    }
}

extern "C" void kernel_launch(void* const* d_in, const int* in_sizes, int n_in,
                              void* d_out, int out_size)
{
    const float* x      = (const float*)d_in[0];
    const float* ref    = (const float*)d_in[1];
    const float* enc_w1 = (const float*)d_in[2];
    const float* enc_b1 = (const float*)d_in[3];
    const float* bn1_g  = (const float*)d_in[4];
    const float* bn1_b  = (const float*)d_in[5];
    const float* enc_w2 = (const float*)d_in[6];
    const float* enc_b2 = (const float*)d_in[7];
    const float* bn2_g  = (const float*)d_in[8];
    const float* bn2_b  = (const float*)d_in[9];
    const float* mu_w   = (const float*)d_in[10];
    const float* mu_b   = (const float*)d_in[11];
    const float* lv_w   = (const float*)d_in[12];
    const float* lv_b   = (const float*)d_in[13];
    const float* dec_w1 = (const float*)d_in[14];
    const float* dec_b1 = (const float*)d_in[15];
    const float* dbn1_g = (const float*)d_in[16];
    const float* dbn1_b = (const float*)d_in[17];
    const float* dec_w2 = (const float*)d_in[18];
    const float* dec_b2 = (const float*)d_in[19];
    const float* dbn2_g = (const float*)d_in[20];
    const float* dbn2_b = (const float*)d_in[21];
    const float* dec_w3 = (const float*)d_in[22];
    const float* dec_b3 = (const float*)d_in[23];

    float* out = (float*)d_out;

    float *p_rm, *p_rp, *p_vec, *p_mu, *p_lv, *p_vdec;
    cudaGetSymbolAddress((void**)&p_rm,   g_rm);
    cudaGetSymbolAddress((void**)&p_rp,   g_rp);
    cudaGetSymbolAddress((void**)&p_vec,  g_vec);
    cudaGetSymbolAddress((void**)&p_mu,   g_mu);
    cudaGetSymbolAddress((void**)&p_lv,   g_lv);
    cudaGetSymbolAddress((void**)&p_vdec, g_vdec);

    const long long need = (long long)NBATCH * 4096 + 2LL * NBATCH * 32;  // 17039360
    float* mu_dst = ((long long)out_size == need) ? out + (size_t)NBATCH * 4096 : p_mu;
    float* lv_dst = ((long long)out_size == need) ? out + (size_t)NBATCH * 4096 + (size_t)NBATCH * 32 : p_lv;

    prep_ref_kernel<<<1, 256, DYN_B>>>(ref, p_rm, p_rp);
    log_map_kernel<<<NBATCH, 256, DYN_B>>>(x, p_rm, p_rp, p_vec);

    mlp_fused_kernel<<<NBATCH / 4, 128>>>(p_vec,
        enc_w1, enc_b1, bn1_g, bn1_b,
        enc_w2, enc_b2, bn2_g, bn2_b,
        mu_w, mu_b, lv_w, lv_b,
        dec_w1, dec_b1, dbn1_g, dbn1_b,
        dec_w2, dec_b2, dbn2_g, dbn2_b,
        dec_w3, dec_b3,
        mu_dst, lv_dst, p_vdec);

    exp_map_kernel<<<NBATCH, 256, DYN_B>>>(ref, p_vdec, out);
}

// round 17
// speedup vs baseline: 1.9704x; 1.1666x over previous
#include <cuda_runtime.h>
#include <math.h>

#define NCH    64
#define PITCH  68
#define NBATCH 4096
#define SPD    2080
#define EPSV   1e-6f
#define BN_SC  0.9999950000375f
#define ROT_TOL 1e-6f
#define HMAT   (64 * PITCH)

__device__ float g_rm[NCH * NCH];
__device__ float g_rp[NCH * NCH];
__device__ float g_vec [(size_t)NBATCH * SPD];
__device__ float g_mu  [(size_t)NBATCH * 32];
__device__ float g_lv  [(size_t)NBATCH * 32];
__device__ float g_vdec[(size_t)NBATCH * SPD];

__device__ __forceinline__ void iu_decode(int u, int& i, int& j)
{
    int lo = 0, hi = 63;
    while (lo < hi) {
        int mid = (lo + hi + 1) >> 1;
        if (((mid * (129 - mid)) >> 1) <= u) lo = mid; else hi = mid - 1;
    }
    i = lo;
    j = lo + (u - ((lo * (129 - lo)) >> 1));
}

// ---------- 256-thread 64x64 GEMM, scalar loads, in-place capable (barrier protocol) ----------
template<int AP, int BP, bool BT, bool SC>
__device__ __forceinline__ void bgemm(const float* __restrict__ Ao,
                                      const float* __restrict__ Bo,
                                      const float* __restrict__ ksc,
                                      float* __restrict__ C, int tid)
{
    const int i0 = (tid >> 4) * 4, j0 = (tid & 15) * 4;
    float acc[4][4];
#pragma unroll
    for (int r = 0; r < 4; r++)
#pragma unroll
        for (int c = 0; c < 4; c++) acc[r][c] = 0.f;
    for (int k = 0; k < 64; k++) {
        float a[4], b[4];
#pragma unroll
        for (int r = 0; r < 4; r++) a[r] = Ao[(i0 + r) * AP + k];
        if (SC) {
            float f = ksc[k];
#pragma unroll
            for (int r = 0; r < 4; r++) a[r] *= f;
        }
#pragma unroll
        for (int c = 0; c < 4; c++)
            b[c] = BT ? Bo[(j0 + c) * BP + k] : Bo[k * BP + j0 + c];
#pragma unroll
        for (int r = 0; r < 4; r++)
#pragma unroll
            for (int c = 0; c < 4; c++) acc[r][c] += a[r] * b[c];
    }
    __syncthreads();
#pragma unroll
    for (int r = 0; r < 4; r++)
#pragma unroll
        for (int c = 0; c < 4; c++)
            C[(i0 + r) * PITCH + j0 + c] = acc[r][c];
    __syncthreads();
}

__device__ __forceinline__ void bgemm_vtv(const float* __restrict__ Vt,
                                          const float* __restrict__ d,
                                          float* __restrict__ C, int tid)
{
    const int i0 = (tid >> 4) * 4, j0 = (tid & 15) * 4;
    float acc[4][4];
#pragma unroll
    for (int r = 0; r < 4; r++)
#pragma unroll
        for (int c = 0; c < 4; c++) acc[r][c] = 0.f;
    for (int t = 0; t < 64; t++) {
        const float* row = Vt + t * PITCH;
        float dk = d[t];
        float a[4], b[4];
#pragma unroll
        for (int r = 0; r < 4; r++) a[r] = row[i0 + r] * dk;
#pragma unroll
        for (int c = 0; c < 4; c++) b[c] = row[j0 + c];
#pragma unroll
        for (int r = 0; r < 4; r++)
#pragma unroll
            for (int c = 0; c < 4; c++) acc[r][c] += a[r] * b[c];
    }
    __syncthreads();
#pragma unroll
    for (int r = 0; r < 4; r++)
#pragma unroll
        for (int c = 0; c < 4; c++)
            C[(i0 + r) * PITCH + j0 + c] = acc[r][c];
    __syncthreads();
}

// ---------- float4 in-place GEMM: C = alpha*(A@B) + (ADDI ? I : 0) ----------
template<int AP, int BP, bool ADDI>
__device__ __forceinline__ void bgemm_f4(const float* __restrict__ Ao,
                                         const float* __restrict__ Bo,
                                         float alpha, float* __restrict__ C, int tid)
{
    const int i0 = (tid >> 4) * 4, j0 = (tid & 15) * 4;
    float acc[4][4];
#pragma unroll
    for (int r = 0; r < 4; r++)
#pragma unroll
        for (int c = 0; c < 4; c++) acc[r][c] = 0.f;
    for (int k4 = 0; k4 < 64; k4 += 4) {
        float4 a[4], br[4];
#pragma unroll
        for (int r = 0; r < 4; r++) a[r] = *(const float4*)(Ao + (i0 + r) * AP + k4);
#pragma unroll
        for (int kk = 0; kk < 4; kk++) br[kk] = *(const float4*)(Bo + (k4 + kk) * BP + j0);
#pragma unroll
        for (int r = 0; r < 4; r++) {
            acc[r][0] += a[r].x * br[0].x + a[r].y * br[1].x + a[r].z * br[2].x + a[r].w * br[3].x;
            acc[r][1] += a[r].x * br[0].y + a[r].y * br[1].y + a[r].z * br[2].y + a[r].w * br[3].y;
            acc[r][2] += a[r].x * br[0].z + a[r].y * br[1].z + a[r].z * br[2].z + a[r].w * br[3].z;
            acc[r][3] += a[r].x * br[0].w + a[r].y * br[1].w + a[r].z * br[2].w + a[r].w * br[3].w;
        }
    }
    __syncthreads();
#pragma unroll
    for (int r = 0; r < 4; r++)
#pragma unroll
        for (int c = 0; c < 4; c++) {
            float v = acc[r][c] * alpha;
            if (ADDI && (i0 + r == j0 + c)) v += 1.f;
            C[(i0 + r) * PITCH + j0 + c] = v;
        }
    __syncthreads();
}

// ---------- one parallel-order Jacobi sweep (256 threads, thresholded) ----------
template<bool WITHV>
__device__ __forceinline__ void jacobi_sweep(float* __restrict__ A, float* __restrict__ Vt,
                                             int lane, int warp)
{
    for (int r = 0; r < 63; r++) {
        int p, q;
        if (lane == 0) { p = 63; q = r; }
        else {
            p = lane + r;      if (p >= 63) p -= 63;
            q = 63 - lane + r; if (q >= 63) q -= 63;
        }
        float app = A[p * PITCH + p], aqq = A[q * PITCH + q];
        float apq = 0.5f * (A[p * PITCH + q] + A[q * PITCH + p]);
        float c = 1.f, s = 0.f;
        if (fabsf(apq) > 1e-36f) {
            float tau = (aqq - app) / (2.f * apq);
            float t = copysignf(1.f, tau) / (fabsf(tau) + sqrtf(1.f + tau * tau));
            c = rsqrtf(1.f + t * t);
            s = t * c;
            if (fabsf(s) < ROT_TOL) { c = 1.f; s = 0.f; }
        }
        __syncthreads();
#pragma unroll
        for (int n = 0; n < 4; n++) {
            int a = warp + 8 * n;
            float ca = __shfl_sync(0xffffffffu, c, a);
            float sa = __shfl_sync(0xffffffffu, s, a);
            int   pa = __shfl_sync(0xffffffffu, p, a);
            int   qa = __shfl_sync(0xffffffffu, q, a);
            bool rowrot = (sa != 0.f);
            if (rowrot || (s != 0.f)) {
                float x00 = A[pa * PITCH + p], x01 = A[pa * PITCH + q];
                float x10 = A[qa * PITCH + p], x11 = A[qa * PITCH + q];
                float t00 = ca * x00 - sa * x10, t01 = ca * x01 - sa * x11;
                float t10 = sa * x00 + ca * x10, t11 = sa * x01 + ca * x11;
                A[pa * PITCH + p] = c * t00 - s * t01;
                A[pa * PITCH + q] = s * t00 + c * t01;
                A[qa * PITCH + p] = c * t10 - s * t11;
                A[qa * PITCH + q] = s * t10 + c * t11;
            }
            if (WITHV && rowrot) {
                float2* Pp = reinterpret_cast<float2*>(Vt + pa * PITCH) + lane;
                float2* Pq = reinterpret_cast<float2*>(Vt + qa * PITCH) + lane;
                float2 vp = *Pp, vq = *Pq;
                float2 np, nq;
                np.x = ca * vp.x - sa * vq.x; np.y = ca * vp.y - sa * vq.y;
                nq.x = sa * vp.x + ca * vq.x; nq.y = sa * vp.y + ca * vq.y;
                *Pp = np; *Pq = nq;
            }
        }
        __syncthreads();
    }
}

template<bool WITHV>
__device__ void jacobi64(float* __restrict__ A, float* __restrict__ Vt, int sweeps,
                         int lane, int warp)
{
    for (int sw = 0; sw < sweeps; sw++)
        jacobi_sweep<WITHV>(A, Vt, lane, warp);
}

#define DYN_B (2 * HMAT * (int)sizeof(float))   // 34816 B

__global__ __launch_bounds__(256, 6)
void prep_ref_kernel(const float* __restrict__ ref,
                     float* __restrict__ rm_out, float* __restrict__ rp_out)
{
    extern __shared__ float smem[];
    float* A  = smem;
    float* Vt = smem + HMAT;
    __shared__ float w1[64], w2[64];
    int tid = threadIdx.x, lane = tid & 31, warp = tid >> 5;
    for (int idx = tid; idx < 4096; idx += 256) {
        int i = idx >> 6, j = idx & 63;
        A[i * PITCH + j] = ref[idx] + ((i == j) ? EPSV : 0.f);
        Vt[i * PITCH + j] = (i == j) ? 1.f : 0.f;
    }
    __syncthreads();
    jacobi64<true>(A, Vt, 12, lane, warp);
    if (tid < 64) {
        float w = fmaxf(A[tid * PITCH + tid], 1e-20f);
        w1[tid] = rsqrtf(w);
        w2[tid] = sqrtf(w);
    }
    __syncthreads();
    bgemm_vtv(Vt, w1, A, tid);
    for (int idx = tid; idx < 4096; idx += 256)
        rm_out[idx] = A[(idx >> 6) * PITCH + (idx & 63)];
    __syncthreads();
    bgemm_vtv(Vt, w2, A, tid);
    for (int idx = tid; idx < 4096; idx += 256)
        rp_out[idx] = A[(idx >> 6) * PITCH + (idx & 63)];
}

__global__ __launch_bounds__(256, 6)
void log_map_kernel(const float* __restrict__ x,
                    const float* __restrict__ rm, const float* __restrict__ rp,
                    float* __restrict__ vec_out)
{
    extern __shared__ float smem[];
    float* A  = smem;
    float* Vt = smem + HMAT;
    __shared__ float w[64];
    int tid = threadIdx.x, lane = tid & 31, warp = tid >> 5;
    const float* X = x + (size_t)blockIdx.x * 4096;
    for (int idx = tid; idx < 1024; idx += 256) {
        int i = idx >> 4, j4 = (idx & 15) << 2;
        *(float4*)(A + i * PITCH + j4) = *(const float4*)(X + i * 64 + j4);
    }
    __syncthreads();
    bgemm<64, PITCH, false, false>(rm, A, nullptr, Vt, tid);   // Vt = rm @ x
    bgemm<PITCH, 64, false, false>(Vt, rm, nullptr, A, tid);   // A = s = rm x rm
    for (int idx = tid; idx < 4096; idx += 256) {
        int i = idx >> 6, j = idx & 63;
        Vt[i * PITCH + j] = (i == j) ? 1.f : 0.f;
    }
    __syncthreads();
    jacobi64<true>(A, Vt, 7, lane, warp);
    if (tid < 64) w[tid] = logf(fmaxf(A[tid * PITCH + tid], 1e-12f));
    __syncthreads();
    bgemm_vtv(Vt, w, A, tid);                                  // A = log_s
    bgemm<64, PITCH, false, false>(rm, A, nullptr, A, tid);    // A = rm @ log_s
    bgemm<PITCH, 64, false, false>(A, rp, nullptr, A, tid);    // A = tang
    float* out = vec_out + (size_t)blockIdx.x * SPD;
    for (int u = tid; u < SPD; u += 256) {
        int i, j; iu_decode(u, i, j);
        out[u] = A[i * PITCH + j];
    }
}

// ---------------- exp_map via scaling-and-squaring + Cholesky PD certificate ----------------
__global__ __launch_bounds__(256, 4)
void exp_map_kernel(const float* __restrict__ ref,
                    const float* __restrict__ vdec_in,
                    float* __restrict__ recon)
{
    extern __shared__ float smem[];
    float* B = smem;
    float* X = smem + HMAT;
    __shared__ float colk[64];
    __shared__ float sh_shift;
    __shared__ int s_fail;
    int tid = threadIdx.x, lane = tid & 31, warp = tid >> 5;
    const float* vd = vdec_in + (size_t)blockIdx.x * SPD;
    const float SCL = 1.f / 64.f;

    for (int u = tid; u < SPD; u += 256) {
        int i, j; iu_decode(u, i, j);
        float v = vd[u];
        if (i == j) B[i * PITCH + i] = (v + EPSV) * SCL;
        else { float sv = v * SCL; B[i * PITCH + j] = sv; B[j * PITCH + i] = sv; }
    }
    for (int idx = tid; idx < 4096; idx += 256) {
        int i = idx >> 6, j = idx & 63;
        X[i * PITCH + j] = (i == j) ? 1.f : 0.f;
    }
    if (tid == 0) s_fail = 0;
    __syncthreads();

#pragma unroll
    for (int k = 6; k >= 1; k--)
        bgemm_f4<PITCH, PITCH, true>(B, X, 1.f / (float)k, X, tid);
#pragma unroll
    for (int q = 0; q < 6; q++)
        bgemm_f4<PITCH, PITCH, false>(X, X, 1.f, X, tid);

    bgemm_f4<64, PITCH, false>(ref, X, 1.f, B, tid);   // B = R = ref @ exp_a

    for (int idx = tid; idx < 4096; idx += 256) {
        int i = idx >> 6, j = idx & 63;
        float v = (i >= j) ? B[i * PITCH + j] : B[j * PITCH + i];
        X[i * PITCH + j] = v - ((i == j) ? EPSV : 0.f);
    }
    __syncthreads();

    for (int k = 0; k < 64; k++) {
        float piv = X[k * PITCH + k];
        if (piv < 1e-5f) {
            if (tid == 0) s_fail = 1;
            __syncthreads();
            break;
        }
        if (tid > k && tid < 64) colk[tid] = X[tid * PITCH + k];
        __syncthreads();
        int n = 63 - k;
        if (n > 0) {
            float inv = 1.f / piv;
            for (int idx = tid; idx < n * n; idx += 256) {
                int i = k + 1 + idx / n, j = k + 1 + idx % n;
                X[i * PITCH + j] -= colk[i] * colk[j] * inv;
            }
        }
        __syncthreads();
    }

    float shf = 0.f;
    if (s_fail) {
        for (int idx = tid; idx < 4096; idx += 256) {
            int i = idx >> 6, j = idx & 63;
            X[i * PITCH + j] = (i >= j) ? B[i * PITCH + j] : B[j * PITCH + i];
        }
        __syncthreads();
        for (int sw = 0; sw < 8; sw++)
            jacobi_sweep<false>(X, nullptr, lane, warp);
        if (tid == 0) {
            float m = X[0];
            for (int t = 1; t < 64; t++) m = fminf(m, X[t * PITCH + t]);
            sh_shift = fmaxf(EPSV - m, 0.f);
        }
        __syncthreads();
        shf = sh_shift;
    }

    float* out = recon + (size_t)blockIdx.x * 4096;
    for (int idx = tid; idx < 1024; idx += 256) {
        int i = idx >> 4, j4 = (idx & 15) << 2;
        float4 v = *(const float4*)(B + i * PITCH + j4);
        if (i >= j4 && i < j4 + 4) ((float*)&v)[i - j4] += shf;
        *(float4*)(out + i * 64 + j4) = v;
    }
}

// ---------------- fused MLP: 4 items per 128-thread block, float4 big layers ----------------
__global__ void mlp_fused_kernel(
    const float* __restrict__ vec,
    const float* __restrict__ W1, const float* __restrict__ b1,
    const float* __restrict__ g1, const float* __restrict__ bb1,
    const float* __restrict__ W2, const float* __restrict__ b2,
    const float* __restrict__ g2, const float* __restrict__ bb2,
    const float* __restrict__ Wmu, const float* __restrict__ bmu,
    const float* __restrict__ Wlv, const float* __restrict__ blv,
    const float* __restrict__ D1, const float* __restrict__ db1,
    const float* __restrict__ dg1, const float* __restrict__ dbb1,
    const float* __restrict__ D2, const float* __restrict__ db2,
    const float* __restrict__ dg2, const float* __restrict__ dbb2,
    const float* __restrict__ D3, const float* __restrict__ db3,
    float* __restrict__ mu_out, float* __restrict__ lv_out,
    float* __restrict__ vdec_out)
{
    __shared__ __align__(16) float sv[4][SPD];
    __shared__ __align__(16) float h1[4][128], h2[4][64], zz[4][32], d1[4][64], d2[4][128];
    const int tid = threadIdx.x;
    const size_t b0 = (size_t)blockIdx.x * 4;
#pragma unroll
    for (int it = 0; it < 4; it++) {
        const float4* src = (const float4*)(vec + (b0 + it) * SPD);
        float4* dst = (float4*)sv[it];
        for (int u = tid; u < SPD / 4; u += 128) dst[u] = src[u];
    }
    __syncthreads();
    // enc1: neuron tid, K=2080, float4
    {
        float a0 = 0.f, a1 = 0.f, a2 = 0.f, a3 = 0.f;
        const float4* wr = (const float4*)(W1 + (size_t)tid * SPD);
        const float4* s0 = (const float4*)sv[0];
        const float4* s1 = (const float4*)sv[1];
        const float4* s2 = (const float4*)sv[2];
        const float4* s3 = (const float4*)sv[3];
        for (int k = 0; k < SPD / 4; k++) {
            float4 w4 = wr[k];
            float4 v;
            v = s0[k]; a0 += v.x * w4.x + v.y * w4.y + v.z * w4.z + v.w * w4.w;
            v = s1[k]; a1 += v.x * w4.x + v.y * w4.y + v.z * w4.z + v.w * w4.w;
            v = s2[k]; a2 += v.x * w4.x + v.y * w4.y + v.z * w4.z + v.w * w4.w;
            v = s3[k]; a3 += v.x * w4.x + v.y * w4.y + v.z * w4.z + v.w * w4.w;
        }
        float bs = b1[tid], scl = g1[tid] * BN_SC, sh = bb1[tid];
        float u;
        u = a0 + bs; u = (u >= 0.f) ? u : 0.2f * u; h1[0][tid] = u * scl + sh;
        u = a1 + bs; u = (u >= 0.f) ? u : 0.2f * u; h1[1][tid] = u * scl + sh;
        u = a2 + bs; u = (u >= 0.f) ? u : 0.2f * u; h1[2][tid] = u * scl + sh;
        u = a3 + bs; u = (u >= 0.f) ? u : 0.2f * u; h1[3][tid] = u * scl + sh;
    }
    __syncthreads();
    if (tid < 64) {
        float a0 = 0.f, a1 = 0.f, a2 = 0.f, a3 = 0.f;
        const float4* wr = (const float4*)(W2 + tid * 128);
        const float4* q0 = (const float4*)h1[0];
        const float4* q1 = (const float4*)h1[1];
        const float4* q2 = (const float4*)h1[2];
        const float4* q3 = (const float4*)h1[3];
        for (int k = 0; k < 32; k++) {
            float4 w4 = wr[k];
            float4 v;
            v = q0[k]; a0 += v.x * w4.x + v.y * w4.y + v.z * w4.z + v.w * w4.w;
            v = q1[k]; a1 += v.x * w4.x + v.y * w4.y + v.z * w4.z + v.w * w4.w;
            v = q2[k]; a2 += v.x * w4.x + v.y * w4.y + v.z * w4.z + v.w * w4.w;
            v = q3[k]; a3 += v.x * w4.x + v.y * w4.y + v.z * w4.z + v.w * w4.w;
        }
        float bs = b2[tid], scl = g2[tid] * BN_SC, sh = bb2[tid];
        float u;
        u = a0 + bs; u = (u >= 0.f) ? u : 0.2f * u; h2[0][tid] = u * scl + sh;
        u = a1 + bs; u = (u >= 0.f) ? u : 0.2f * u; h2[1][tid] = u * scl + sh;
        u = a2 + bs; u = (u >= 0.f) ? u : 0.2f * u; h2[2][tid] = u * scl + sh;
        u = a3 + bs; u = (u >= 0.f) ? u : 0.2f * u; h2[3][tid] = u * scl + sh;
    }
    __syncthreads();
    if (tid < 32) {
        float am[4] = {0.f, 0.f, 0.f, 0.f}, al[4] = {0.f, 0.f, 0.f, 0.f};
        const float* wm = Wmu + tid * 64;
        const float* wl = Wlv + tid * 64;
        for (int k = 0; k < 64; k++) {
            float wmv = wm[k], wlv_ = wl[k];
#pragma unroll
            for (int it = 0; it < 4; it++) {
                am[it] += h2[it][k] * wmv;
                al[it] += h2[it][k] * wlv_;
            }
        }
        float bm = bmu[tid], bl = blv[tid];
#pragma unroll
        for (int it = 0; it < 4; it++) {
            float m = am[it] + bm;
            zz[it][tid] = m;
            mu_out[(b0 + it) * 32 + tid] = m;
            lv_out[(b0 + it) * 32 + tid] = al[it] + bl;
        }
    }
    __syncthreads();
    if (tid < 64) {
        float a[4] = {0.f, 0.f, 0.f, 0.f};
        const float* wr = D1 + tid * 32;
        for (int k = 0; k < 32; k++) {
            float wv = wr[k];
#pragma unroll
            for (int it = 0; it < 4; it++) a[it] += zz[it][k] * wv;
        }
        float bs = db1[tid], scl = dg1[tid] * BN_SC, sh = dbb1[tid];
#pragma unroll
        for (int it = 0; it < 4; it++) {
            float u = a[it] + bs; u = (u >= 0.f) ? u : 0.2f * u;
            d1[it][tid] = u * scl + sh;
        }
    }
    __syncthreads();
    {
        float a[4] = {0.f, 0.f, 0.f, 0.f};
        const float* wr = D2 + tid * 64;
        for (int k = 0; k < 64; k++) {
            float wv = wr[k];
#pragma unroll
            for (int it = 0; it < 4; it++) a[it] += d1[it][k] * wv;
        }
        float bs = db2[tid], scl = dg2[tid] * BN_SC, sh = dbb2[tid];
#pragma unroll
        for (int it = 0; it < 4; it++) {
            float u = a[it] + bs; u = (u >= 0.f) ? u : 0.2f * u;
            d2[it][tid] = u * scl + sh;
        }
    }
    __syncthreads();
    // dec3: float4 over K=128
    for (int j = tid; j < SPD; j += 128) {
        float a0 = 0.f, a1 = 0.f, a2 = 0.f, a3 = 0.f;
        const float4* wr = (const float4*)(D3 + (size_t)j * 128);
        const float4* q0 = (const float4*)d2[0];
        const float4* q1 = (const float4*)d2[1];
        const float4* q2 = (const float4*)d2[2];
        const float4* q3 = (const float4*)d2[3];
#pragma unroll 8
        for (int k = 0; k < 32; k++) {
            float4 w4 = wr[k];
            float4 v;
            v = q0[k]; a0 += v.x * w4.x + v.y * w4.y + v.z * w4.z + v.w * w4.w;
            v = q1[k]; a1 += v.x * w4.x + v.y * w4.y + v.z * w4.z + v.w * w4.w;
            v = q2[k]; a2 += v.x * w4.x + v.y * w4.y + v.z * w4.z + v.w * w4.w;
            v = q3[k]; a3 += v.x * w4.x + v.y * w4.y + v.z * w4.z + v.w * w4.w;
        }
        float bs = db3[j];
        vdec_out[(b0 + 0) * SPD + j] = a0 + bs;
        vdec_out[(b0 + 1) * SPD + j] = a1 + bs;
        vdec_out[(b0 + 2) * SPD + j] = a2 + bs;
        vdec_out[(b0 + 3) * SPD + j] = a3 + bs;
    }
}

extern "C" void kernel_launch(void* const* d_in, const int* in_sizes, int n_in,
                              void* d_out, int out_size)
{
    const float* x      = (const float*)d_in[0];
    const float* ref    = (const float*)d_in[1];
    const float* enc_w1 = (const float*)d_in[2];
    const float* enc_b1 = (const float*)d_in[3];
    const float* bn1_g  = (const float*)d_in[4];
    const float* bn1_b  = (const float*)d_in[5];
    const float* enc_w2 = (const float*)d_in[6];
    const float* enc_b2 = (const float*)d_in[7];
    const float* bn2_g  = (const float*)d_in[8];
    const float* bn2_b  = (const float*)d_in[9];
    const float* mu_w   = (const float*)d_in[10];
    const float* mu_b   = (const float*)d_in[11];
    const float* lv_w   = (const float*)d_in[12];
    const float* lv_b   = (const float*)d_in[13];
    const float* dec_w1 = (const float*)d_in[14];
    const float* dec_b1 = (const float*)d_in[15];
    const float* dbn1_g = (const float*)d_in[16];
    const float* dbn1_b = (const float*)d_in[17];
    const float* dec_w2 = (const float*)d_in[18];
    const float* dec_b2 = (const float*)d_in[19];
    const float* dbn2_g = (const float*)d_in[20];
    const float* dbn2_b = (const float*)d_in[21];
    const float* dec_w3 = (const float*)d_in[22];
    const float* dec_b3 = (const float*)d_in[23];

    float* out = (float*)d_out;

    float *p_rm, *p_rp, *p_vec, *p_mu, *p_lv, *p_vdec;
    cudaGetSymbolAddress((void**)&p_rm,   g_rm);
    cudaGetSymbolAddress((void**)&p_rp,   g_rp);
    cudaGetSymbolAddress((void**)&p_vec,  g_vec);
    cudaGetSymbolAddress((void**)&p_mu,   g_mu);
    cudaGetSymbolAddress((void**)&p_lv,   g_lv);
    cudaGetSymbolAddress((void**)&p_vdec, g_vdec);

    const long long need = (long long)NBATCH * 4096 + 2LL * NBATCH * 32;  // 17039360
    float* mu_dst = ((long long)out_size == need) ? out + (size_t)NBATCH * 4096 : p_mu;
    float* lv_dst = ((long long)out_size == need) ? out + (size_t)NBATCH * 4096 + (size_t)NBATCH * 32 : p_lv;

    prep_ref_kernel<<<1, 256, DYN_B>>>(ref, p_rm, p_rp);
    log_map_kernel<<<NBATCH, 256, DYN_B>>>(x, p_rm, p_rp, p_vec);

    mlp_fused_kernel<<<NBATCH / 4, 128>>>(p_vec,
        enc_w1, enc_b1, bn1_g, bn1_b,
        enc_w2, enc_b2, bn2_g, bn2_b,
        mu_w, mu_b, lv_w, lv_b,
        dec_w1, dec_b1, dbn1_g, dbn1_b,
        dec_w2, dec_b2, dbn2_g, dbn2_b,
        dec_w3, dec_b3,
        mu_dst, lv_dst, p_vdec);

    exp_map_kernel<<<NBATCH, 256, DYN_B>>>(ref, p_vdec, out);
}